// round 3
// baseline (speedup 1.0000x reference)
#include <cuda_runtime.h>
#include <cuda_bf16.h>

#define NQ 11
#define NDIM 2048                         // 1 << NQ
#define NLAYERS 5
#define NANG (3 * NQ * (NLAYERS + 1))     // 198 variational angles
#define W_SIZE NANG

__device__ __forceinline__ float2 cmul(float2 a, float2 b) {
    return make_float2(a.x * b.x - a.y * b.y, a.x * b.y + a.y * b.x);
}
// acc += a * conj(b)
__device__ __forceinline__ float2 cmadd_conj(float2 acc, float2 a, float2 b) {
    acc.x = fmaf(a.x, b.x, fmaf(a.y, b.y, acc.x));
    acc.y = fmaf(a.y, b.x, fmaf(-a.x, b.y, acc.y));
    return acc;
}

__device__ __forceinline__ int decode_dimA(const int* p, int B, int out_size) {
    int d = -1;
    if (p) {
        int v = p[0];
        if (v >= 1 && v <= NQ) {
            d = v;
        } else {
            float f = __int_as_float(v);
            if (f >= 0.5f && f <= 11.5f) d = (int)(f + 0.5f);
        }
    }
    if (d < 1 || d > NQ) {
        for (int t = 1; t <= NQ; t++) {
            long long nc = (long long)B << (2 * t);
            if (nc == (long long)out_size || 2 * nc == (long long)out_size) { d = t; break; }
        }
    }
    if (d < 1 || d > NQ) d = 5;
    return d;
}

__global__ __launch_bounds__(1024, 1)
void qsim_kernel(const float* __restrict__ x,
                 const float* __restrict__ w,
                 const int* __restrict__ dimA_p,
                 void* __restrict__ out_v,
                 int B, int out_size)
{
    __shared__ float2 st[NDIM];       // statevector, 16 KB
    __shared__ float2 cs[NANG];       // (cos, sin) of half-angles for all 198 gates
    __shared__ float2 embcs[NQ];      // (cos, sin) of embedding half-angles

    const int tid = threadIdx.x;
    const int b   = blockIdx.x;

    // ---- Precompute (cos, sin) of every half-angle ----
    if (tid < NANG) {
        float s, c;
        sincosf(0.5f * w[tid], &s, &c);
        cs[tid] = make_float2(c, s);
    }
    if (tid < NQ) {
        float s, c;
        sincosf(0.5f * x[b * NQ + tid], &s, &c);
        embcs[tid] = make_float2(c, s);
    }
    // ---- Init |0...0> ----
    st[tid]        = (tid == 0) ? make_float2(1.f, 0.f) : make_float2(0.f, 0.f);
    st[tid + 1024] = make_float2(0.f, 0.f);
    __syncthreads();

    // ======== gate sweep helpers (as lambdas over tid) ========
    // Ry-type (real rotation) on qubit q: [[c,-s],[s,c]]
    auto ry_sweep = [&](int q, float c, float s) {
        const int bp = NQ - 1 - q;
        const int lowmask = (1 << bp) - 1;
        int i0 = ((tid >> bp) << (bp + 1)) | (tid & lowmask);
        int i1 = i0 | (1 << bp);
        float2 a0 = st[i0], a1 = st[i1];
        st[i0] = make_float2(c * a0.x - s * a1.x, c * a0.y - s * a1.y);
        st[i1] = make_float2(s * a0.x + c * a1.x, s * a0.y + c * a1.y);
        __syncthreads();
    };
    // Rz on qubit q: diag(e^{-it/2}, e^{+it/2})
    auto rz_sweep = [&](int q, float c, float s) {
        const int bp = NQ - 1 - q;
        float2 em = make_float2(c, -s);
        float2 ep = make_float2(c,  s);
        #pragma unroll
        for (int base = 0; base < NDIM; base += 1024) {
            int idx = base + tid;
            float2 ph = ((idx >> bp) & 1) ? ep : em;
            st[idx] = cmul(ph, st[idx]);
        }
        __syncthreads();
    };

    // ---- Angle embedding: Ry(x_q) on each qubit (qubit 0 is MSB) ----
    for (int q = 0; q < NQ; q++) {
        ry_sweep(q, embcs[q].x, embcs[q].y);
    }

    // ---- Variational circuit: literal Ry, Rz, Ry per qubit per layer ----
    for (int l = 0; l < NLAYERS; l++) {
        for (int q = 0; q < NQ; q++) {
            int base = l * (3 * NQ) + q * 3;
            ry_sweep(q, cs[base].x,     cs[base].y);
            rz_sweep(q, cs[base + 1].x, cs[base + 1].y);
            ry_sweep(q, cs[base + 2].x, cs[base + 2].y);
        }
        // ring of CNOTs: control q, target (q+1) % NQ
        for (int q = 0; q < NQ; q++) {
            const int t  = (q + 1) % NQ;
            const int bc = NQ - 1 - q;
            const int bt = NQ - 1 - t;
            if (tid < (NDIM / 4)) {
                const int lo = (bc < bt) ? bc : bt;
                const int hi = (bc < bt) ? bt : bc;
                int i = tid;
                i = ((i >> lo) << (lo + 1)) | (i & ((1 << lo) - 1));
                i = ((i >> hi) << (hi + 1)) | (i & ((1 << hi) - 1));
                i |= (1 << bc);              // control = 1
                int j = i | (1 << bt);       // target partner
                float2 tmp = st[i];
                st[i] = st[j];
                st[j] = tmp;
            }
            __syncthreads();
        }
    }
    // final YZY layer
    for (int q = 0; q < NQ; q++) {
        int base = NLAYERS * (3 * NQ) + q * 3;
        ry_sweep(q, cs[base].x,     cs[base].y);
        rz_sweep(q, cs[base + 1].x, cs[base + 1].y);
        ry_sweep(q, cs[base + 2].x, cs[base + 2].y);
    }

    // ---- Partial trace: rho[j,k] = sum_i psi[i*dA+j] * conj(psi[i*dA+k]) ----
    const int dimA = decode_dimA(dimA_p, B, out_size);
    const int dA   = 1 << dimA;
    const int dB   = NDIM >> dimA;
    const int nOut = dA * dA;
    const bool real_only = ((long long)B * nOut == (long long)out_size);

    for (int o = tid; o < nOut; o += blockDim.x) {
        int j = o / dA;
        int k = o - j * dA;
        float2 acc = make_float2(0.f, 0.f);
        for (int i = 0; i < dB; i++) {
            acc = cmadd_conj(acc, st[i * dA + j], st[i * dA + k]);
        }
        if (real_only) {
            ((float*)out_v)[b * nOut + o] = acc.x;           // Re(rho) only
        } else {
            ((float2*)out_v)[b * nOut + o] = acc;            // interleaved complex
        }
    }
}

extern "C" void kernel_launch(void* const* d_in, const int* in_sizes, int n_in,
                              void* d_out, int out_size) {
    // Bind by element count (sizes are unique): w=198, dimA=1, x=the rest (B*11)
    const float* x = nullptr;
    const float* w = nullptr;
    const int* dimA_p = nullptr;
    int x_size = 0;
    for (int i = 0; i < n_in; i++) {
        if (in_sizes[i] == W_SIZE) {
            w = (const float*)d_in[i];
        } else if (in_sizes[i] == 1) {
            dimA_p = (const int*)d_in[i];
        } else {
            x = (const float*)d_in[i];
            x_size = in_sizes[i];
        }
    }
    if (!x) { x = (const float*)d_in[0]; x_size = in_sizes[0]; }
    if (!w) { w = (const float*)d_in[1]; }

    int B = x_size / NQ;                      // 176 / 11 = 16
    qsim_kernel<<<B, 1024>>>(x, w, dimA_p, d_out, B, out_size);
}

// round 4
// speedup vs baseline: 1.9212x; 1.9212x over previous
#include <cuda_runtime.h>
#include <cuda_bf16.h>

#define NQ 11
#define NDIM 2048                 // 1 << NQ
#define NLAYERS 5
#define NBLK (NLAYERS + 1)        // 6 YZY blocks
#define NMAT (NBLK * NQ)          // 66 fused matrices
#define W_SIZE (3 * NMAT)         // 198

__device__ __forceinline__ float2 cmul(float2 a, float2 b) {
    return make_float2(a.x * b.x - a.y * b.y, a.x * b.y + a.y * b.x);
}
// acc += a * b (complex)
__device__ __forceinline__ float2 cfma2(float2 a, float2 b, float2 acc) {
    acc.x = fmaf(a.x, b.x, fmaf(-a.y, b.y, acc.x));
    acc.y = fmaf(a.x, b.y, fmaf( a.y, b.x, acc.y));
    return acc;
}
__device__ __forceinline__ int ins0(int x, int b) {
    return ((x >> b) << (b + 1)) | (x & ((1 << b) - 1));
}

__device__ __forceinline__ int decode_dimA(const int* p, int B, int out_size) {
    int d = -1;
    if (p) {
        int v = p[0];
        if (v >= 1 && v <= NQ) d = v;
        else {
            float f = __int_as_float(v);
            if (f >= 0.5f && f <= 11.5f) d = (int)(f + 0.5f);
        }
    }
    if (d < 1 || d > NQ) {
        for (int t = 1; t <= NQ; t++) {
            long long nc = (long long)B << (2 * t);
            if (nc == (long long)out_size || 2 * nc == (long long)out_size) { d = t; break; }
        }
    }
    if (d < 1 || d > NQ) d = 5;
    return d;
}

__global__ __launch_bounds__(1024, 1)
void qsim_kernel(const float* __restrict__ x,
                 const float* __restrict__ w,
                 const int* __restrict__ dimA_p,
                 void* __restrict__ out_v,
                 int B, int out_size)
{
    __shared__ float2 st[NDIM];                 // statevector (16 KB)
    __shared__ float2 fm[NMAT][4];              // fused YZY matrices
    __shared__ float2 u[NQ][2];                 // product-init coefs (embed*YZY0 col0)
    __shared__ unsigned vtab[NLAYERS][NQ];      // pair-XOR vectors for blocks 1..5
    __shared__ unsigned rtab[NLAYERS][NQ];      // logical-bit parity masks
    __shared__ unsigned gfin[NQ];               // final G columns (trace permutation)
    __shared__ int physA[32], physB[64];        // trace index tables (dimA==5 path)
    __shared__ float partial[4][1024];          // trace partial sums (16 KB)

    const int tid = threadIdx.x;
    const int b   = blockIdx.x;

    // ---- Fused M = Ry(t2) Rz(t1) Ry(t0), 66 matrices ----
    if (tid < NMAT) {
        int base = tid * 3;
        float t0 = w[base], t1 = w[base + 1], t2 = w[base + 2];
        float c0, s0, c1, s1, c2, s2;
        sincosf(0.5f * t0, &s0, &c0);
        sincosf(0.5f * t1, &s1, &c1);
        sincosf(0.5f * t2, &s2, &c2);
        float2 em = make_float2(c1, -s1);
        float2 ep = make_float2(c1,  s1);
        fm[tid][0] = make_float2( c2*c0*em.x - s2*s0*ep.x,  c2*c0*em.y - s2*s0*ep.y);
        fm[tid][1] = make_float2(-c2*s0*em.x - s2*c0*ep.x, -c2*s0*em.y - s2*c0*ep.y);
        fm[tid][2] = make_float2( s2*c0*em.x + c2*s0*ep.x,  s2*c0*em.y + c2*s0*ep.y);
        fm[tid][3] = make_float2(-s2*s0*em.x + c2*c0*ep.x, -s2*s0*em.y + c2*c0*ep.y);
    }
    // ---- GF(2) CNOT-ring tracking tables (thread 0; unrolled const-index ops) ----
    if (tid == 0) {
        unsigned frow[NQ], gcol[NQ];
        #pragma unroll
        for (int i = 0; i < NQ; i++) { frow[i] = 1u << i; gcol[i] = 1u << i; }
        for (int L = 0; L < NLAYERS; L++) {
            #pragma unroll
            for (int q = 0; q < NQ; q++) {
                const int bc = NQ - 1 - q;
                const int bt = NQ - 1 - ((q + 1) % NQ);
                frow[bt] ^= frow[bc];          // F' = C F
                gcol[bc] ^= gcol[bt];          // G' = G C
            }
            #pragma unroll
            for (int q = 0; q < NQ; q++) {
                vtab[L][q] = gcol[NQ - 1 - q];
                rtab[L][q] = frow[NQ - 1 - q];
            }
        }
        #pragma unroll
        for (int i = 0; i < NQ; i++) gfin[i] = gcol[i];
    }
    __syncthreads();

    // ---- Embedding fused into block 0: u_q = (M0q * E_q) |0> ----
    if (tid < NQ) {
        float sh, ch;
        sincosf(0.5f * x[b * NQ + tid], &sh, &ch);
        const float2* M = fm[tid];
        u[tid][0] = make_float2(M[0].x*ch + M[1].x*sh, M[0].y*ch + M[1].y*sh);
        u[tid][1] = make_float2(M[2].x*ch + M[3].x*sh, M[2].y*ch + M[3].y*sh);
    }
    // ---- Trace permutation tables (logical -> physical) ----
    if (tid >= 64 && tid < 96) {
        int j = tid - 64; unsigned ph = 0;
        #pragma unroll
        for (int bit = 0; bit < 5; bit++) if ((j >> bit) & 1) ph ^= gfin[bit];
        physA[j] = (int)ph;
    }
    if (tid < 64) {
        int i = tid; unsigned ph = 0;
        #pragma unroll
        for (int bit = 0; bit < 6; bit++) if ((i >> bit) & 1) ph ^= gfin[5 + bit];
        physB[i] = (int)ph;
    }
    __syncthreads();

    // ---- Product-state init: st[p] = prod_q u_q[bit_{10-q}(p)] ----
    {
        float2 rest = u[1][(tid >> 9) & 1];
        #pragma unroll
        for (int q = 2; q <= 10; q++) rest = cmul(rest, u[q][(tid >> (10 - q)) & 1]);
        st[tid]        = cmul(u[0][0], rest);
        st[tid + 1024] = cmul(u[0][1], rest);
    }
    __syncthreads();

    // ---- Blocks 1..5 (CNOT rings are free F/G updates, already in tables) ----
    for (int L = 0; L < NLAYERS; L++) {
        const int mbase = (L + 1) * NQ;
        // 5 double passes: qubits (0,1)(2,3)(4,5)(6,7)(8,9)
        #pragma unroll
        for (int gpair = 0; gpair < 5; gpair++) {
            const unsigned v1 = vtab[L][2 * gpair],     r1 = rtab[L][2 * gpair];
            const unsigned v2 = vtab[L][2 * gpair + 1], r2 = rtab[L][2 * gpair + 1];
            const float2* M1 = fm[mbase + 2 * gpair];
            const float2* M2 = fm[mbase + 2 * gpair + 1];
            if (tid < 512) {
                int b1 = __ffs(v1) - 1;
                unsigned v2p = ((v2 >> b1) & 1) ? (v1 ^ v2) : v2;
                int b2 = __ffs(v2p) - 1;
                int lo = min(b1, b2), hi = max(b1, b2);
                int p = ins0(ins0(tid, lo), hi);
                int t1 = __popc(r1 & (unsigned)p) & 1;
                int t2 = __popc(r2 & (unsigned)p) & 1;
                int p01 = p ^ (int)v1, p10 = p ^ (int)v2, p11 = p01 ^ (int)v2;
                float2 z00 = st[p], z01 = st[p10], z10 = st[p01], z11 = st[p11];
                // qubit-1 gate with rows/cols swapped by t1: A[a][a'] = M1[((t1^a)<<1)|(t1^a')]
                float2 A00 = M1[t1 ? 3 : 0], A01 = M1[t1 ? 2 : 1];
                float2 A10 = M1[t1 ? 1 : 2], A11 = M1[t1 ? 0 : 3];
                float2 n00 = cfma2(A01, z10, cmul(A00, z00));
                float2 n10 = cfma2(A11, z10, cmul(A10, z00));
                float2 n01 = cfma2(A01, z11, cmul(A00, z01));
                float2 n11 = cfma2(A11, z11, cmul(A10, z01));
                // qubit-2 gate swapped by t2
                float2 B00 = M2[t2 ? 3 : 0], B01 = M2[t2 ? 2 : 1];
                float2 B10 = M2[t2 ? 1 : 2], B11 = M2[t2 ? 0 : 3];
                z00 = cfma2(B01, n01, cmul(B00, n00));
                z01 = cfma2(B11, n01, cmul(B10, n00));
                z10 = cfma2(B01, n11, cmul(B00, n10));
                z11 = cfma2(B11, n11, cmul(B10, n10));
                st[p]   = z00; st[p10] = z01; st[p01] = z10; st[p11] = z11;
            }
            __syncthreads();
        }
        // single pass: qubit 10
        {
            const unsigned v = vtab[L][10], r = rtab[L][10];
            const float2* M = fm[mbase + 10];
            int b1 = __ffs(v) - 1;
            int p = ins0(tid, b1);
            int t = __popc(r & (unsigned)p) & 1;
            int p1 = p ^ (int)v;
            float2 z0 = st[p], z1 = st[p1];
            float2 A00 = M[t ? 3 : 0], A01 = M[t ? 2 : 1];
            float2 A10 = M[t ? 1 : 2], A11 = M[t ? 0 : 3];
            st[p]  = cfma2(A01, z1, cmul(A00, z0));
            st[p1] = cfma2(A11, z1, cmul(A10, z0));
            __syncthreads();
        }
    }

    // ---- Partial trace ----
    const int dimA = decode_dimA(dimA_p, B, out_size);
    const int dA   = 1 << dimA;
    const int dB   = NDIM >> dimA;
    const int nOut = dA * dA;
    const bool real_only = ((long long)B * nOut == (long long)out_size);

    if (dimA == 5 && real_only) {
        // Re(rho) = real syrk, i-split into 4 groups, 2x2 register tiles
        int g  = tid >> 8;
        int s  = tid & 255;
        int j0 = (s & 15) * 2;
        int k0 = (s >> 4) * 2;
        int pa_j0 = physA[j0], pa_j1 = physA[j0 + 1];
        int pa_k0 = physA[k0], pa_k1 = physA[k0 + 1];
        float d00 = 0.f, d01 = 0.f, d10 = 0.f, d11 = 0.f;
        #pragma unroll
        for (int ii = 0; ii < 16; ii++) {
            int pb = physB[g * 16 + ii];
            float2 aj0 = st[pb ^ pa_j0];
            float2 aj1 = st[pb ^ pa_j1];
            float2 ak0 = st[pb ^ pa_k0];
            float2 ak1 = st[pb ^ pa_k1];
            d00 = fmaf(aj0.x, ak0.x, fmaf(aj0.y, ak0.y, d00));
            d01 = fmaf(aj0.x, ak1.x, fmaf(aj0.y, ak1.y, d01));
            d10 = fmaf(aj1.x, ak0.x, fmaf(aj1.y, ak0.y, d10));
            d11 = fmaf(aj1.x, ak1.x, fmaf(aj1.y, ak1.y, d11));
        }
        partial[g][j0 * 32 + k0]            = d00;
        partial[g][j0 * 32 + k0 + 1]        = d01;
        partial[g][(j0 + 1) * 32 + k0]      = d10;
        partial[g][(j0 + 1) * 32 + k0 + 1]  = d11;
        __syncthreads();
        ((float*)out_v)[b * 1024 + tid] =
            partial[0][tid] + partial[1][tid] + partial[2][tid] + partial[3][tid];
    } else {
        // Generic fallback: compute physical index on the fly
        for (int o = tid; o < nOut; o += blockDim.x) {
            int j = o / dA;
            int k = o - j * dA;
            float2 acc = make_float2(0.f, 0.f);
            for (int i = 0; i < dB; i++) {
                int lj = i * dA + j, lk = i * dA + k;
                unsigned pj = 0, pk = 0;
                #pragma unroll
                for (int bit = 0; bit < NQ; bit++) {
                    if ((lj >> bit) & 1) pj ^= gfin[bit];
                    if ((lk >> bit) & 1) pk ^= gfin[bit];
                }
                float2 a = st[pj], c = st[pk];
                acc.x = fmaf(a.x, c.x, fmaf(a.y, c.y, acc.x));
                acc.y = fmaf(a.y, c.x, fmaf(-a.x, c.y, acc.y));
            }
            if (real_only) ((float*)out_v)[b * nOut + o] = acc.x;
            else           ((float2*)out_v)[b * nOut + o] = acc;
        }
    }
}

extern "C" void kernel_launch(void* const* d_in, const int* in_sizes, int n_in,
                              void* d_out, int out_size) {
    // Bind by element count (unique sizes): w=198, dimA=1, x = B*11
    const float* x = nullptr;
    const float* w = nullptr;
    const int* dimA_p = nullptr;
    int x_size = 0;
    for (int i = 0; i < n_in; i++) {
        if (in_sizes[i] == W_SIZE) w = (const float*)d_in[i];
        else if (in_sizes[i] == 1) dimA_p = (const int*)d_in[i];
        else { x = (const float*)d_in[i]; x_size = in_sizes[i]; }
    }
    if (!x) { x = (const float*)d_in[0]; x_size = in_sizes[0]; }
    if (!w) { w = (const float*)d_in[1]; }

    int B = x_size / NQ;   // 16
    qsim_kernel<<<B, 1024>>>(x, w, dimA_p, d_out, B, out_size);
}

// round 5
// speedup vs baseline: 2.0269x; 1.0550x over previous
#include <cuda_runtime.h>
#include <cuda_bf16.h>

#define NQ 11
#define NDIM 2048                 // 1 << NQ
#define NLAYERS 5
#define NBLK (NLAYERS + 1)        // 6 YZY blocks
#define NMAT (NBLK * NQ)          // 66 fused matrices
#define W_SIZE (3 * NMAT)         // 198

__device__ __forceinline__ float2 cmul(float2 a, float2 b) {
    return make_float2(a.x * b.x - a.y * b.y, a.x * b.y + a.y * b.x);
}
// acc += a * b (complex)
__device__ __forceinline__ float2 cfma2(float2 a, float2 b, float2 acc) {
    acc.x = fmaf(a.x, b.x, fmaf(-a.y, b.y, acc.x));
    acc.y = fmaf(a.x, b.y, fmaf( a.y, b.x, acc.y));
    return acc;
}
__device__ __forceinline__ int ins0(int x, int b) {
    return ((x >> b) << (b + 1)) | (x & ((1 << b) - 1));
}

__device__ __forceinline__ int decode_dimA(const int* p, int B, int out_size) {
    int d = -1;
    if (p) {
        int v = p[0];
        if (v >= 1 && v <= NQ) d = v;
        else {
            float f = __int_as_float(v);
            if (f >= 0.5f && f <= 11.5f) d = (int)(f + 0.5f);
        }
    }
    if (d < 1 || d > NQ) {
        for (int t = 1; t <= NQ; t++) {
            long long nc = (long long)B << (2 * t);
            if (nc == (long long)out_size || 2 * nc == (long long)out_size) { d = t; break; }
        }
    }
    if (d < 1 || d > NQ) d = 5;
    return d;
}

// Apply 2x2 gate M (with row/col swap t) along axis S of register array z[]
#define APPLY_GATE(Z, NELEM, M, T, S)                                          \
    do {                                                                       \
        float2 A00 = (M)[(T) ? 3 : 0], A01 = (M)[(T) ? 2 : 1];                 \
        float2 A10 = (M)[(T) ? 1 : 2], A11 = (M)[(T) ? 0 : 3];                 \
        _Pragma("unroll")                                                      \
        for (int k = 0; k < (NELEM); k++) {                                    \
            if (k & (S)) continue;                                             \
            float2 z0 = (Z)[k], z1 = (Z)[k + (S)];                             \
            (Z)[k]       = cfma2(A01, z1, cmul(A00, z0));                      \
            (Z)[k + (S)] = cfma2(A11, z1, cmul(A10, z0));                      \
        }                                                                      \
    } while (0)

__global__ __launch_bounds__(256, 1)
void qsim_kernel(const float* __restrict__ x,
                 const float* __restrict__ w,
                 const int* __restrict__ dimA_p,
                 void* __restrict__ out_v,
                 int B, int out_size)
{
    __shared__ float2 st[NDIM];                 // statevector (16 KB)
    __shared__ float2 fm[NMAT][4];              // fused YZY matrices
    __shared__ float2 u[NQ][2];                 // embed*YZY0 column coefs
    __shared__ unsigned vtab[NLAYERS][NQ];      // pair-XOR vectors (G columns)
    __shared__ unsigned rtab[NLAYERS][NQ];      // parity masks (F rows)
    __shared__ unsigned gfin[NQ];               // final G columns
    __shared__ int physA[32], physB[64];        // trace index tables
    __shared__ float partial[4][1024];          // trace partials (16 KB)

    const int tid = threadIdx.x;
    const int b   = blockIdx.x;

    // ---- Fused M = Ry(t2) Rz(t1) Ry(t0) ----
    if (tid < NMAT) {
        int base = tid * 3;
        float t0 = w[base], t1 = w[base + 1], t2 = w[base + 2];
        float c0, s0, c1, s1, c2, s2;
        sincosf(0.5f * t0, &s0, &c0);
        sincosf(0.5f * t1, &s1, &c1);
        sincosf(0.5f * t2, &s2, &c2);
        float2 em = make_float2(c1, -s1);
        float2 ep = make_float2(c1,  s1);
        fm[tid][0] = make_float2( c2*c0*em.x - s2*s0*ep.x,  c2*c0*em.y - s2*s0*ep.y);
        fm[tid][1] = make_float2(-c2*s0*em.x - s2*c0*ep.x, -c2*s0*em.y - s2*c0*ep.y);
        fm[tid][2] = make_float2( s2*c0*em.x + c2*s0*ep.x,  s2*c0*em.y + c2*s0*ep.y);
        fm[tid][3] = make_float2(-s2*s0*em.x + c2*c0*ep.x, -s2*s0*em.y + c2*c0*ep.y);
    }
    // ---- GF(2) CNOT-ring tracking ----
    if (tid == 0) {
        unsigned frow[NQ], gcol[NQ];
        #pragma unroll
        for (int i = 0; i < NQ; i++) { frow[i] = 1u << i; gcol[i] = 1u << i; }
        for (int L = 0; L < NLAYERS; L++) {
            #pragma unroll
            for (int q = 0; q < NQ; q++) {
                const int bc = NQ - 1 - q;
                const int bt = NQ - 1 - ((q + 1) % NQ);
                frow[bt] ^= frow[bc];
                gcol[bc] ^= gcol[bt];
            }
            #pragma unroll
            for (int q = 0; q < NQ; q++) {
                vtab[L][q] = gcol[NQ - 1 - q];
                rtab[L][q] = frow[NQ - 1 - q];
            }
        }
        #pragma unroll
        for (int i = 0; i < NQ; i++) gfin[i] = gcol[i];
    }
    __syncthreads();

    // ---- Embedding fused into block 0 + trace permutation tables ----
    if (tid < NQ) {
        float sh, ch;
        sincosf(0.5f * x[b * NQ + tid], &sh, &ch);
        const float2* M = fm[tid];
        u[tid][0] = make_float2(M[0].x*ch + M[1].x*sh, M[0].y*ch + M[1].y*sh);
        u[tid][1] = make_float2(M[2].x*ch + M[3].x*sh, M[2].y*ch + M[3].y*sh);
    }
    if (tid >= 64 && tid < 96) {
        int j = tid - 64; unsigned ph = 0;
        #pragma unroll
        for (int bit = 0; bit < 5; bit++) if ((j >> bit) & 1) ph ^= gfin[bit];
        physA[j] = (int)ph;
    }
    if (tid < 64) {
        int i = tid; unsigned ph = 0;
        #pragma unroll
        for (int bit = 0; bit < 6; bit++) if ((i >> bit) & 1) ph ^= gfin[5 + bit];
        physB[i] = (int)ph;
    }
    __syncthreads();

    // ---- Product-state init: 8 consecutive amps per thread ----
    {
        // p = (tid << 3) | k ; qubit q <-> bit (10 - q)
        float2 hi = cmul(u[0][(tid >> 7) & 1], u[1][(tid >> 6) & 1]);
        hi = cmul(hi, u[2][(tid >> 5) & 1]);
        hi = cmul(hi, u[3][(tid >> 4) & 1]);
        hi = cmul(hi, u[4][(tid >> 3) & 1]);
        hi = cmul(hi, u[5][(tid >> 2) & 1]);
        hi = cmul(hi, u[6][(tid >> 1) & 1]);
        hi = cmul(hi, u[7][tid & 1]);
        #pragma unroll
        for (int k = 0; k < 8; k++) {
            float2 lo = cmul(u[8][(k >> 2) & 1], cmul(u[9][(k >> 1) & 1], u[10][k & 1]));
            st[(tid << 3) | k] = cmul(hi, lo);
        }
    }
    __syncthreads();

    // ---- Blocks 1..5: per layer, 3 passes of 3 qubits + 1 pass of 2 ----
    for (int L = 0; L < NLAYERS; L++) {
        const int mbase = (L + 1) * NQ;
        // three 3-qubit passes: qubits (0,1,2), (3,4,5), (6,7,8)
        #pragma unroll
        for (int grp = 0; grp < 3; grp++) {
            const int q0 = grp * 3;
            const unsigned v1 = vtab[L][q0],     r1 = rtab[L][q0];
            const unsigned v2 = vtab[L][q0 + 1], r2 = rtab[L][q0 + 1];
            const unsigned v3 = vtab[L][q0 + 2], r3 = rtab[L][q0 + 2];
            const float2* M1 = fm[mbase + q0];
            const float2* M2 = fm[mbase + q0 + 1];
            const float2* M3 = fm[mbase + q0 + 2];
            // pivot reduction
            int b1 = __ffs((int)v1) - 1;
            unsigned w2 = ((v2 >> b1) & 1) ? (v2 ^ v1) : v2;
            unsigned w3 = ((v3 >> b1) & 1) ? (v3 ^ v1) : v3;
            int b2 = __ffs((int)w2) - 1;
            unsigned w3b = ((w3 >> b2) & 1) ? (w3 ^ w2) : w3;
            int b3 = __ffs((int)w3b) - 1;
            int lo  = min(b1, min(b2, b3));
            int hi  = max(b1, max(b2, b3));
            int mid = b1 + b2 + b3 - lo - hi;
            int p = ins0(ins0(ins0(tid, lo), mid), hi);
            int t1 = __popc(r1 & (unsigned)p) & 1;
            int t2 = __popc(r2 & (unsigned)p) & 1;
            int t3 = __popc(r3 & (unsigned)p) & 1;
            int addr[8];
            #pragma unroll
            for (int k = 0; k < 8; k++)
                addr[k] = p ^ ((k & 1) ? (int)v1 : 0) ^ ((k & 2) ? (int)v2 : 0)
                            ^ ((k & 4) ? (int)v3 : 0);
            float2 z[8];
            #pragma unroll
            for (int k = 0; k < 8; k++) z[k] = st[addr[k]];
            APPLY_GATE(z, 8, M1, t1, 1);
            APPLY_GATE(z, 8, M2, t2, 2);
            APPLY_GATE(z, 8, M3, t3, 4);
            __syncthreads();   // ensure all reads done before overwriting (coset-disjoint, but cheap safety for compiler ordering)
            #pragma unroll
            for (int k = 0; k < 8; k++) st[addr[k]] = z[k];
            __syncthreads();
        }
        // one 2-qubit pass: qubits (9, 10) — two cosets per thread
        {
            const unsigned v1 = vtab[L][9],  r1 = rtab[L][9];
            const unsigned v2 = vtab[L][10], r2 = rtab[L][10];
            const float2* M1 = fm[mbase + 9];
            const float2* M2 = fm[mbase + 10];
            int b1 = __ffs((int)v1) - 1;
            unsigned w2 = ((v2 >> b1) & 1) ? (v2 ^ v1) : v2;
            int b2 = __ffs((int)w2) - 1;
            int lo = min(b1, b2), hi = max(b1, b2);
            int addr[2][4];
            float2 z[2][4];
            #pragma unroll
            for (int cc = 0; cc < 2; cc++) {
                int ct = tid + 256 * cc;
                int p = ins0(ins0(ct, lo), hi);
                int t1 = __popc(r1 & (unsigned)p) & 1;
                int t2 = __popc(r2 & (unsigned)p) & 1;
                #pragma unroll
                for (int k = 0; k < 4; k++)
                    addr[cc][k] = p ^ ((k & 1) ? (int)v1 : 0) ^ ((k & 2) ? (int)v2 : 0);
                #pragma unroll
                for (int k = 0; k < 4; k++) z[cc][k] = st[addr[cc][k]];
                APPLY_GATE(z[cc], 4, M1, t1, 1);
                APPLY_GATE(z[cc], 4, M2, t2, 2);
            }
            __syncthreads();
            #pragma unroll
            for (int cc = 0; cc < 2; cc++)
                #pragma unroll
                for (int k = 0; k < 4; k++) st[addr[cc][k]] = z[cc][k];
            __syncthreads();
        }
    }

    // ---- Partial trace: Re(rho[j,k]) = sum_i Re(psi_ij psi_ik*) ----
    const int dimA = decode_dimA(dimA_p, B, out_size);
    const int dA   = 1 << dimA;
    const int dB   = NDIM >> dimA;
    const int nOut = dA * dA;
    const bool real_only = ((long long)B * nOut == (long long)out_size);

    if (dimA == 5 && real_only) {
        // 4 i-groups x 64 threads; 4x4 register tiles over 16 i's each
        int g  = tid >> 6;
        int ss = tid & 63;
        int j0 = (ss & 7) * 4;
        int k0 = (ss >> 3) * 4;
        int paj[4], pak[4];
        #pragma unroll
        for (int d = 0; d < 4; d++) { paj[d] = physA[j0 + d]; pak[d] = physA[k0 + d]; }
        float acc[4][4];
        #pragma unroll
        for (int a = 0; a < 4; a++)
            #pragma unroll
            for (int c = 0; c < 4; c++) acc[a][c] = 0.f;
        #pragma unroll
        for (int ii = 0; ii < 16; ii++) {
            int pb = physB[g * 16 + ii];
            float2 aj[4], ak[4];
            #pragma unroll
            for (int d = 0; d < 4; d++) { aj[d] = st[pb ^ paj[d]]; ak[d] = st[pb ^ pak[d]]; }
            #pragma unroll
            for (int a = 0; a < 4; a++)
                #pragma unroll
                for (int c = 0; c < 4; c++)
                    acc[a][c] = fmaf(aj[a].x, ak[c].x, fmaf(aj[a].y, ak[c].y, acc[a][c]));
        }
        #pragma unroll
        for (int a = 0; a < 4; a++)
            #pragma unroll
            for (int c = 0; c < 4; c++)
                partial[g][(j0 + a) * 32 + (k0 + c)] = acc[a][c];
        __syncthreads();
        #pragma unroll
        for (int m = 0; m < 4; m++) {
            int o = tid * 4 + m;
            ((float*)out_v)[b * 1024 + o] =
                partial[0][o] + partial[1][o] + partial[2][o] + partial[3][o];
        }
    } else {
        // Generic fallback
        for (int o = tid; o < nOut; o += blockDim.x) {
            int j = o / dA;
            int k = o - j * dA;
            float2 acc = make_float2(0.f, 0.f);
            for (int i = 0; i < dB; i++) {
                int lj = i * dA + j, lk = i * dA + k;
                unsigned pj = 0, pk = 0;
                #pragma unroll
                for (int bit = 0; bit < NQ; bit++) {
                    if ((lj >> bit) & 1) pj ^= gfin[bit];
                    if ((lk >> bit) & 1) pk ^= gfin[bit];
                }
                float2 a = st[pj], c = st[pk];
                acc.x = fmaf(a.x, c.x, fmaf(a.y, c.y, acc.x));
                acc.y = fmaf(a.y, c.x, fmaf(-a.x, c.y, acc.y));
            }
            if (real_only) ((float*)out_v)[b * nOut + o] = acc.x;
            else           ((float2*)out_v)[b * nOut + o] = acc;
        }
    }
}

extern "C" void kernel_launch(void* const* d_in, const int* in_sizes, int n_in,
                              void* d_out, int out_size) {
    // Bind by element count (unique sizes): w=198, dimA=1, x = B*11
    const float* x = nullptr;
    const float* w = nullptr;
    const int* dimA_p = nullptr;
    int x_size = 0;
    for (int i = 0; i < n_in; i++) {
        if (in_sizes[i] == W_SIZE) w = (const float*)d_in[i];
        else if (in_sizes[i] == 1) dimA_p = (const int*)d_in[i];
        else { x = (const float*)d_in[i]; x_size = in_sizes[i]; }
    }
    if (!x) { x = (const float*)d_in[0]; x_size = in_sizes[0]; }
    if (!w) { w = (const float*)d_in[1]; }

    int B = x_size / NQ;   // 16
    qsim_kernel<<<B, 256>>>(x, w, dimA_p, d_out, B, out_size);
}

// round 6
// speedup vs baseline: 2.1856x; 1.0783x over previous
#include <cuda_runtime.h>
#include <cuda_bf16.h>

#define NQ 11
#define NDIM 2048                 // 1 << NQ
#define NLAYERS 5
#define NBLK (NLAYERS + 1)        // 6 YZY blocks
#define NMAT (NBLK * NQ)          // 66 fused matrices
#define W_SIZE (3 * NMAT)         // 198

__device__ __forceinline__ float2 cmul(float2 a, float2 b) {
    return make_float2(a.x * b.x - a.y * b.y, a.x * b.y + a.y * b.x);
}
// acc += a * b (complex)
__device__ __forceinline__ float2 cfma2(float2 a, float2 b, float2 acc) {
    acc.x = fmaf(a.x, b.x, fmaf(-a.y, b.y, acc.x));
    acc.y = fmaf(a.x, b.y, fmaf( a.y, b.x, acc.y));
    return acc;
}
__device__ __forceinline__ int ins0(int x, int b) {
    return ((x >> b) << (b + 1)) | (x & ((1 << b) - 1));
}

__device__ __forceinline__ int decode_dimA(const int* p, int B, int out_size) {
    int d = -1;
    if (p) {
        int v = p[0];
        if (v >= 1 && v <= NQ) d = v;
        else {
            float f = __int_as_float(v);
            if (f >= 0.5f && f <= 11.5f) d = (int)(f + 0.5f);
        }
    }
    if (d < 1 || d > NQ) {
        for (int t = 1; t <= NQ; t++) {
            long long nc = (long long)B << (2 * t);
            if (nc == (long long)out_size || 2 * nc == (long long)out_size) { d = t; break; }
        }
    }
    if (d < 1 || d > NQ) d = 5;
    return d;
}

// Apply 2x2 gate M (with row/col swap t) along stride S of register array z[]
#define APPLY_GATE(Z, NELEM, M, T, S)                                          \
    do {                                                                       \
        float2 A00 = (M)[(T) ? 3 : 0], A01 = (M)[(T) ? 2 : 1];                 \
        float2 A10 = (M)[(T) ? 1 : 2], A11 = (M)[(T) ? 0 : 3];                 \
        _Pragma("unroll")                                                      \
        for (int k = 0; k < (NELEM); k++) {                                    \
            if (k & (S)) continue;                                             \
            float2 z0 = (Z)[k], z1 = (Z)[k + (S)];                             \
            (Z)[k]       = cfma2(A01, z1, cmul(A00, z0));                      \
            (Z)[k + (S)] = cfma2(A11, z1, cmul(A10, z0));                      \
        }                                                                      \
    } while (0)

__global__ __launch_bounds__(512, 1)
void qsim_kernel(const float* __restrict__ x,
                 const float* __restrict__ w,
                 const int* __restrict__ dimA_p,
                 void* __restrict__ out_v,
                 int B, int out_size)
{
    __shared__ float2 st[NDIM];                 // statevector (16 KB)
    __shared__ float2 fm[NMAT][4];              // fused YZY matrices
    __shared__ float2 u[NQ][2];                 // embed*YZY0 column coefs
    __shared__ unsigned vtab[NLAYERS][NQ];      // pair-XOR vectors (G columns)
    __shared__ unsigned rtab[NLAYERS][NQ];      // parity masks (F rows)
    __shared__ unsigned gfin[NQ];               // final G columns
    __shared__ int physA[32], physB[64];        // trace index tables
    __shared__ float partial[4][1024];          // trace partials (16 KB)

    const int tid = threadIdx.x;
    const int b   = blockIdx.x;

    // ---- Fused M = Ry(t2) Rz(t1) Ry(t0) ----
    if (tid < NMAT) {
        int base = tid * 3;
        float t0 = w[base], t1 = w[base + 1], t2 = w[base + 2];
        float c0, s0, c1, s1, c2, s2;
        sincosf(0.5f * t0, &s0, &c0);
        sincosf(0.5f * t1, &s1, &c1);
        sincosf(0.5f * t2, &s2, &c2);
        float2 em = make_float2(c1, -s1);
        float2 ep = make_float2(c1,  s1);
        fm[tid][0] = make_float2( c2*c0*em.x - s2*s0*ep.x,  c2*c0*em.y - s2*s0*ep.y);
        fm[tid][1] = make_float2(-c2*s0*em.x - s2*c0*ep.x, -c2*s0*em.y - s2*c0*ep.y);
        fm[tid][2] = make_float2( s2*c0*em.x + c2*s0*ep.x,  s2*c0*em.y + c2*s0*ep.y);
        fm[tid][3] = make_float2(-s2*s0*em.x + c2*c0*ep.x, -s2*s0*em.y + c2*c0*ep.y);
    }
    // ---- GF(2) CNOT-ring tracking ----
    if (tid == 0) {
        unsigned frow[NQ], gcol[NQ];
        #pragma unroll
        for (int i = 0; i < NQ; i++) { frow[i] = 1u << i; gcol[i] = 1u << i; }
        for (int L = 0; L < NLAYERS; L++) {
            #pragma unroll
            for (int q = 0; q < NQ; q++) {
                const int bc = NQ - 1 - q;
                const int bt = NQ - 1 - ((q + 1) % NQ);
                frow[bt] ^= frow[bc];
                gcol[bc] ^= gcol[bt];
            }
            #pragma unroll
            for (int q = 0; q < NQ; q++) {
                vtab[L][q] = gcol[NQ - 1 - q];
                rtab[L][q] = frow[NQ - 1 - q];
            }
        }
        #pragma unroll
        for (int i = 0; i < NQ; i++) gfin[i] = gcol[i];
    }
    __syncthreads();

    // ---- Embedding fused into block 0 + trace permutation tables ----
    if (tid < NQ) {
        float sh, ch;
        sincosf(0.5f * x[b * NQ + tid], &sh, &ch);
        const float2* M = fm[tid];
        u[tid][0] = make_float2(M[0].x*ch + M[1].x*sh, M[0].y*ch + M[1].y*sh);
        u[tid][1] = make_float2(M[2].x*ch + M[3].x*sh, M[2].y*ch + M[3].y*sh);
    }
    if (tid >= 64 && tid < 96) {
        int j = tid - 64; unsigned ph = 0;
        #pragma unroll
        for (int bit = 0; bit < 5; bit++) if ((j >> bit) & 1) ph ^= gfin[bit];
        physA[j] = (int)ph;
    }
    if (tid < 64) {
        int i = tid; unsigned ph = 0;
        #pragma unroll
        for (int bit = 0; bit < 6; bit++) if ((i >> bit) & 1) ph ^= gfin[5 + bit];
        physB[i] = (int)ph;
    }
    __syncthreads();

    // ---- Product-state init: 4 consecutive amps per thread ----
    {
        // p = (tid << 2) | k ; qubit q <-> bit (10 - q)
        float2 hi = cmul(u[0][(tid >> 8) & 1], u[1][(tid >> 7) & 1]);
        hi = cmul(hi, u[2][(tid >> 6) & 1]);
        hi = cmul(hi, u[3][(tid >> 5) & 1]);
        hi = cmul(hi, u[4][(tid >> 4) & 1]);
        hi = cmul(hi, u[5][(tid >> 3) & 1]);
        hi = cmul(hi, u[6][(tid >> 2) & 1]);
        hi = cmul(hi, u[7][(tid >> 1) & 1]);
        hi = cmul(hi, u[8][tid & 1]);
        #pragma unroll
        for (int k = 0; k < 4; k++) {
            float2 lo = cmul(u[9][(k >> 1) & 1], u[10][k & 1]);
            st[(tid << 2) | k] = cmul(hi, lo);
        }
    }
    __syncthreads();

    // ---- Blocks 1..5: per layer, 5 two-qubit passes + 1 single-qubit pass ----
    for (int L = 0; L < NLAYERS; L++) {
        const int mbase = (L + 1) * NQ;
        #pragma unroll
        for (int gpair = 0; gpair < 5; gpair++) {
            const int q0 = 2 * gpair;
            const unsigned v1 = vtab[L][q0],     r1 = rtab[L][q0];
            const unsigned v2 = vtab[L][q0 + 1], r2 = rtab[L][q0 + 1];
            const float2* M1 = fm[mbase + q0];
            const float2* M2 = fm[mbase + q0 + 1];
            int b1 = __ffs((int)v1) - 1;
            unsigned w2 = ((v2 >> b1) & 1) ? (v2 ^ v1) : v2;
            int b2 = __ffs((int)w2) - 1;
            int lo = min(b1, b2), hi = max(b1, b2);
            int p = ins0(ins0(tid, lo), hi);
            int t1 = __popc(r1 & (unsigned)p) & 1;
            int t2 = __popc(r2 & (unsigned)p) & 1;
            int a0 = p, a1 = p ^ (int)v1, a2 = p ^ (int)v2, a3 = a1 ^ (int)v2;
            float2 z[4];
            z[0] = st[a0]; z[1] = st[a1]; z[2] = st[a2]; z[3] = st[a3];
            APPLY_GATE(z, 4, M1, t1, 1);
            APPLY_GATE(z, 4, M2, t2, 2);
            st[a0] = z[0]; st[a1] = z[1]; st[a2] = z[2]; st[a3] = z[3];
            __syncthreads();
        }
        // single-qubit pass: qubit 10 (two cosets per thread)
        {
            const unsigned v = vtab[L][10], r = rtab[L][10];
            const float2* M = fm[mbase + 10];
            int b1 = __ffs((int)v) - 1;
            int pA = ins0(tid, b1);
            int pB = ins0(tid + 512, b1);
            int tA = __popc(r & (unsigned)pA) & 1;
            int tB = __popc(r & (unsigned)pB) & 1;
            int pA1 = pA ^ (int)v, pB1 = pB ^ (int)v;
            float2 zA0 = st[pA], zA1 = st[pA1];
            float2 zB0 = st[pB], zB1 = st[pB1];
            {
                float2 A00 = M[tA ? 3 : 0], A01 = M[tA ? 2 : 1];
                float2 A10 = M[tA ? 1 : 2], A11 = M[tA ? 0 : 3];
                st[pA]  = cfma2(A01, zA1, cmul(A00, zA0));
                st[pA1] = cfma2(A11, zA1, cmul(A10, zA0));
            }
            {
                float2 A00 = M[tB ? 3 : 0], A01 = M[tB ? 2 : 1];
                float2 A10 = M[tB ? 1 : 2], A11 = M[tB ? 0 : 3];
                st[pB]  = cfma2(A01, zB1, cmul(A00, zB0));
                st[pB1] = cfma2(A11, zB1, cmul(A10, zB0));
            }
            __syncthreads();
        }
    }

    // ---- Partial trace: Re(rho[j,k]) = sum_i Re(psi_ij psi_ik*) ----
    const int dimA = decode_dimA(dimA_p, B, out_size);
    const int dA   = 1 << dimA;
    const int dB   = NDIM >> dimA;
    const int nOut = dA * dA;
    const bool real_only = ((long long)B * nOut == (long long)out_size);

    if (dimA == 5 && real_only) {
        // 4 i-groups x 128 threads; each thread computes a 2x4 tile over 16 i's
        int g  = tid >> 7;           // 0..3
        int ss = tid & 127;
        int j0 = (ss >> 3) * 2;      // rows: 16 pairs
        int k0 = (ss & 7) * 4;       // cols: 8 quads
        int paj0 = physA[j0], paj1 = physA[j0 + 1];
        int pak[4];
        #pragma unroll
        for (int d = 0; d < 4; d++) pak[d] = physA[k0 + d];
        float acc[2][4];
        #pragma unroll
        for (int a = 0; a < 2; a++)
            #pragma unroll
            for (int c = 0; c < 4; c++) acc[a][c] = 0.f;
        #pragma unroll
        for (int ii = 0; ii < 16; ii++) {
            int pb = physB[g * 16 + ii];
            float2 aj0 = st[pb ^ paj0];
            float2 aj1 = st[pb ^ paj1];
            #pragma unroll
            for (int c = 0; c < 4; c++) {
                float2 ak = st[pb ^ pak[c]];
                acc[0][c] = fmaf(aj0.x, ak.x, fmaf(aj0.y, ak.y, acc[0][c]));
                acc[1][c] = fmaf(aj1.x, ak.x, fmaf(aj1.y, ak.y, acc[1][c]));
            }
        }
        #pragma unroll
        for (int a = 0; a < 2; a++)
            #pragma unroll
            for (int c = 0; c < 4; c++)
                partial[g][(j0 + a) * 32 + (k0 + c)] = acc[a][c];
        __syncthreads();
        #pragma unroll
        for (int m = 0; m < 2; m++) {
            int o = tid * 2 + m;
            ((float*)out_v)[b * 1024 + o] =
                partial[0][o] + partial[1][o] + partial[2][o] + partial[3][o];
        }
    } else {
        // Generic fallback
        for (int o = tid; o < nOut; o += blockDim.x) {
            int j = o / dA;
            int k = o - j * dA;
            float2 acc = make_float2(0.f, 0.f);
            for (int i = 0; i < dB; i++) {
                int lj = i * dA + j, lk = i * dA + k;
                unsigned pj = 0, pk = 0;
                #pragma unroll
                for (int bit = 0; bit < NQ; bit++) {
                    if ((lj >> bit) & 1) pj ^= gfin[bit];
                    if ((lk >> bit) & 1) pk ^= gfin[bit];
                }
                float2 a = st[pj], c = st[pk];
                acc.x = fmaf(a.x, c.x, fmaf(a.y, c.y, acc.x));
                acc.y = fmaf(a.y, c.x, fmaf(-a.x, c.y, acc.y));
            }
            if (real_only) ((float*)out_v)[b * nOut + o] = acc.x;
            else           ((float2*)out_v)[b * nOut + o] = acc;
        }
    }
}

extern "C" void kernel_launch(void* const* d_in, const int* in_sizes, int n_in,
                              void* d_out, int out_size) {
    // Bind by element count (unique sizes): w=198, dimA=1, x = B*11
    const float* x = nullptr;
    const float* w = nullptr;
    const int* dimA_p = nullptr;
    int x_size = 0;
    for (int i = 0; i < n_in; i++) {
        if (in_sizes[i] == W_SIZE) w = (const float*)d_in[i];
        else if (in_sizes[i] == 1) dimA_p = (const int*)d_in[i];
        else { x = (const float*)d_in[i]; x_size = in_sizes[i]; }
    }
    if (!x) { x = (const float*)d_in[0]; x_size = in_sizes[0]; }
    if (!w) { w = (const float*)d_in[1]; }

    int B = x_size / NQ;   // 16
    qsim_kernel<<<B, 512>>>(x, w, dimA_p, d_out, B, out_size);
}